// round 2
// baseline (speedup 1.0000x reference)
#include <cuda_runtime.h>
#include <math.h>

// Problem constants
#define BB 4
#define LL 2048
#define SS 2048
#define DD 1024
#define HH 16
#define HD 64
#define MM (BB * LL)   // 8192 rows for all projection GEMMs

// Scratch (device globals: allocation-free rule)
__device__ float g_Qh[BB * HH * LL * HD];   // [B,H,L,hd] 32MB
__device__ float g_Kh[BB * HH * SS * HD];   // [B,H,S,hd] 32MB
__device__ float g_Vh[BB * HH * SS * HD];   // [B,H,S,hd] 32MB
__device__ float g_AO[BB * LL * DD];        // [B,L,D]    32MB

// ---------------------------------------------------------------------------
// GEMM: Y[m,n] = sum_k X[m,k] * W[n,k]   (x @ W.T, W is [out,in] row-major)
// M=8192, N=1024, K=1024.  128x128x16 tile, 8x8 per-thread, 256 threads.
// SPLIT_HEADS=1: write Y as [B, H, seq, HD] (fused head-split transpose).
// ---------------------------------------------------------------------------
template <int SPLIT_HEADS>
__global__ __launch_bounds__(256) void gemm_xwt_kernel(
    const float* __restrict__ X, const float* __restrict__ W,
    float* __restrict__ Y)
{
    const int BM = 128, BN = 128, BK = 16;
    __shared__ float As[BK][BM + 4];
    __shared__ float Bs[BK][BN + 4];

    const int bm = blockIdx.y * BM;
    const int bn = blockIdx.x * BN;
    const int tid = threadIdx.x;
    const int tx = tid & 15;   // 0..15 -> output col block
    const int ty = tid >> 4;   // 0..15 -> output row block

    float acc[8][8];
#pragma unroll
    for (int i = 0; i < 8; i++)
#pragma unroll
        for (int j = 0; j < 8; j++) acc[i][j] = 0.f;

    for (int kt = 0; kt < DD; kt += BK) {
#pragma unroll
        for (int i = 0; i < 2; i++) {
            int t = tid + i * 256;      // 0..511
            int row = t >> 2;           // 0..127
            int k4 = (t & 3) * 4;       // 0,4,8,12
            float4 a = *(const float4*)(X + (size_t)(bm + row) * DD + kt + k4);
            As[k4 + 0][row] = a.x; As[k4 + 1][row] = a.y;
            As[k4 + 2][row] = a.z; As[k4 + 3][row] = a.w;
            float4 b = *(const float4*)(W + (size_t)(bn + row) * DD + kt + k4);
            Bs[k4 + 0][row] = b.x; Bs[k4 + 1][row] = b.y;
            Bs[k4 + 2][row] = b.z; Bs[k4 + 3][row] = b.w;
        }
        __syncthreads();

#pragma unroll
        for (int k = 0; k < BK; k++) {
            float ra[8], rb[8];
            float4 a0 = *(const float4*)(&As[k][ty * 8]);
            float4 a1 = *(const float4*)(&As[k][ty * 8 + 4]);
            ra[0] = a0.x; ra[1] = a0.y; ra[2] = a0.z; ra[3] = a0.w;
            ra[4] = a1.x; ra[5] = a1.y; ra[6] = a1.z; ra[7] = a1.w;
            float4 b0 = *(const float4*)(&Bs[k][tx * 8]);
            float4 b1 = *(const float4*)(&Bs[k][tx * 8 + 4]);
            rb[0] = b0.x; rb[1] = b0.y; rb[2] = b0.z; rb[3] = b0.w;
            rb[4] = b1.x; rb[5] = b1.y; rb[6] = b1.z; rb[7] = b1.w;
#pragma unroll
            for (int i = 0; i < 8; i++)
#pragma unroll
                for (int j = 0; j < 8; j++)
                    acc[i][j] += ra[i] * rb[j];
        }
        __syncthreads();
    }

    const int n0 = bn + tx * 8;
#pragma unroll
    for (int i = 0; i < 8; i++) {
        int m = bm + ty * 8 + i;
        float4 lo = make_float4(acc[i][0], acc[i][1], acc[i][2], acc[i][3]);
        float4 hi = make_float4(acc[i][4], acc[i][5], acc[i][6], acc[i][7]);
        if (SPLIT_HEADS) {
            // m = b*seq + l ; n = h*HD + hd  ->  [(b*H + h)*seq + l]*HD + hd
            int b = m >> 11;          // /2048
            int l = m & 2047;
            int h = n0 >> 6;
            int hd = n0 & 63;         // 8-col block stays inside one head
            float* dst = Y + (((size_t)(b * HH + h) * LL + l) * HD + hd);
            *(float4*)dst = lo;
            *(float4*)(dst + 4) = hi;
        } else {
            float* dst = Y + (size_t)m * DD + n0;
            *(float4*)dst = lo;
            *(float4*)(dst + 4) = hi;
        }
    }
}

// ---------------------------------------------------------------------------
// Flash attention (causal). 1 thread = 1 query row. BM=128 queries/block,
// key tiles of 64. Online softmax in 8-key chunks (sc[] stays in registers).
// ---------------------------------------------------------------------------
__global__ __launch_bounds__(128) void flash_attn_kernel(
    const float* __restrict__ Qh, const float* __restrict__ Kh,
    const float* __restrict__ Vh, float* __restrict__ AO)
{
    __shared__ float Ks[64][HD + 4];
    __shared__ float Vs[64][HD + 4];

    const int bh = blockIdx.y;          // b*H + h
    const int b = bh >> 4;
    const int h = bh & 15;
    const int l = blockIdx.x * 128 + threadIdx.x;

    const float* Qb = Qh + (size_t)bh * (LL * HD);
    const float* Kb = Kh + (size_t)bh * (SS * HD);
    const float* Vb = Vh + (size_t)bh * (SS * HD);

    float q[64], o[64];
#pragma unroll
    for (int i = 0; i < 16; i++) {
        float4 t = *(const float4*)(Qb + (size_t)l * HD + i * 4);
        q[4 * i + 0] = t.x; q[4 * i + 1] = t.y;
        q[4 * i + 2] = t.z; q[4 * i + 3] = t.w;
    }
#pragma unroll
    for (int d = 0; d < 64; d++) o[d] = 0.f;

    float mx = -1e30f, lsum = 0.f;
    const int ntiles = blockIdx.x * 2 + 2;   // causal: keys <= last query of blk

    for (int jt = 0; jt < ntiles; jt++) {
        const int s0 = jt * 64;
        __syncthreads();
#pragma unroll
        for (int i = 0; i < 8; i++) {
            int t = threadIdx.x + i * 128;   // 0..1023
            int r = t >> 4;
            int c = (t & 15) * 4;
            *(float4*)(&Ks[r][c]) = *(const float4*)(Kb + (size_t)(s0 + r) * HD + c);
            *(float4*)(&Vs[r][c]) = *(const float4*)(Vb + (size_t)(s0 + r) * HD + c);
        }
        __syncthreads();

#pragma unroll 1
        for (int c0 = 0; c0 < 64; c0 += 8) {
            float sc[8];
            float cm = -1e30f;
#pragma unroll
            for (int s = 0; s < 8; s++) {
                float a0 = 0.f, a1 = 0.f, a2 = 0.f, a3 = 0.f;
#pragma unroll
                for (int d4 = 0; d4 < 16; d4++) {
                    float4 kk = *(const float4*)(&Ks[c0 + s][d4 * 4]);
                    a0 += q[d4 * 4 + 0] * kk.x;
                    a1 += q[d4 * 4 + 1] * kk.y;
                    a2 += q[d4 * 4 + 2] * kk.z;
                    a3 += q[d4 * 4 + 3] * kk.w;
                }
                float v = ((a0 + a1) + (a2 + a3)) * 0.125f;
                if (s0 + c0 + s > l) v = -1e30f;   // causal mask
                sc[s] = v;
                cm = fmaxf(cm, v);
            }
            float mnew = fmaxf(mx, cm);
            if (mnew != mx) {
                float corr = __expf(mx - mnew);
                lsum *= corr;
#pragma unroll
                for (int d = 0; d < 64; d++) o[d] *= corr;
                mx = mnew;
            }
#pragma unroll
            for (int s = 0; s < 8; s++) {
                float p = __expf(sc[s] - mx);
                lsum += p;
#pragma unroll
                for (int d4 = 0; d4 < 16; d4++) {
                    float4 vv = *(const float4*)(&Vs[c0 + s][d4 * 4]);
                    o[d4 * 4 + 0] += p * vv.x;
                    o[d4 * 4 + 1] += p * vv.y;
                    o[d4 * 4 + 2] += p * vv.z;
                    o[d4 * 4 + 3] += p * vv.w;
                }
            }
        }
    }

    const float inv = 1.f / lsum;
    float* dst = AO + ((size_t)(b * LL) + l) * DD + h * HD;
#pragma unroll
    for (int i = 0; i < 16; i++) {
        float4 t = make_float4(o[4 * i + 0] * inv, o[4 * i + 1] * inv,
                               o[4 * i + 2] * inv, o[4 * i + 3] * inv);
        *(float4*)(dst + 4 * i) = t;
    }
}

// ---------------------------------------------------------------------------
// Launch
// ---------------------------------------------------------------------------
extern "C" void kernel_launch(void* const* d_in, const int* in_sizes, int n_in,
                              void* d_out, int out_size)
{
    const float* q  = (const float*)d_in[0];
    const float* k  = (const float*)d_in[1];
    const float* v  = (const float*)d_in[2];
    // d_in[3] = mask (causal, known analytically — unused)
    const float* Wq = (const float*)d_in[4];
    const float* Wk = (const float*)d_in[5];
    const float* Wv = (const float*)d_in[6];
    const float* Wo = (const float*)d_in[7];
    float* out = (float*)d_out;

    float *Qh, *Kh, *Vh, *AO;
    cudaGetSymbolAddress((void**)&Qh, g_Qh);
    cudaGetSymbolAddress((void**)&Kh, g_Kh);
    cudaGetSymbolAddress((void**)&Vh, g_Vh);
    cudaGetSymbolAddress((void**)&AO, g_AO);

    dim3 ggrid(DD / 128, MM / 128);   // (8, 64)
    dim3 gblk(256);

    // Projections with fused head-split transpose
    gemm_xwt_kernel<1><<<ggrid, gblk>>>(q, Wq, Qh);
    gemm_xwt_kernel<1><<<ggrid, gblk>>>(k, Wk, Kh);
    gemm_xwt_kernel<1><<<ggrid, gblk>>>(v, Wv, Vh);

    // Causal flash attention -> AO [B,L,D]
    dim3 fgrid(LL / 128, BB * HH);    // (16, 64)
    flash_attn_kernel<<<fgrid, 128>>>(Qh, Kh, Vh, AO);

    // Output projection -> d_out
    gemm_xwt_kernel<0><<<ggrid, gblk>>>(AO, Wo, out);
}

// round 4
// speedup vs baseline: 1.5386x; 1.5386x over previous
#include <cuda_runtime.h>
#include <math.h>
#include <stdint.h>

// Problem constants
#define BB 4
#define LL 2048
#define SS 2048
#define DD 1024
#define HH 16
#define HD 64
#define MM (BB * LL)   // 8192 rows for all projection GEMMs

// Scratch (device globals: allocation-free rule)
__device__ float g_Qh[BB * HH * LL * HD];   // [B,H,L,hd] 32MB
__device__ float g_Kh[BB * HH * SS * HD];   // [B,H,S,hd] 32MB
__device__ float g_Vh[BB * HH * SS * HD];   // [B,H,S,hd] 32MB
__device__ float g_AO[BB * LL * DD];        // [B,L,D]    32MB

// ---------------------------------------------------------------------------
// TF32 tensor-core GEMM: Y[m,n] = sum_k X[m,k] * W[n,k]  (x @ W.T)
// M=8192, N=1024, K=1024. 128x128x16 tile, 8 warps (2x4), warp tile 64x32,
// mma.sync.m16n8k8.tf32, cp.async double-buffered smem.
// SPLIT_HEADS=1: write Y as [B,H,seq,HD] (fused head-split transpose).
// ---------------------------------------------------------------------------
#define GBK 16
#define GSTRIDE 20          // padded row stride in floats (conflict-free)
#define GBUF (128 * GSTRIDE)

__device__ __forceinline__ uint32_t f2tf32(float f) {
    uint32_t r;
    asm("cvt.rna.tf32.f32 %0, %1;" : "=r"(r) : "f"(f));
    return r;
}

__device__ __forceinline__ void mma_tf32(float* d, const uint32_t* a, const uint32_t* b) {
    asm volatile(
        "mma.sync.aligned.m16n8k8.row.col.f32.tf32.tf32.f32 "
        "{%0,%1,%2,%3},{%4,%5,%6,%7},{%8,%9},{%0,%1,%2,%3};"
        : "+f"(d[0]), "+f"(d[1]), "+f"(d[2]), "+f"(d[3])
        : "r"(a[0]), "r"(a[1]), "r"(a[2]), "r"(a[3]), "r"(b[0]), "r"(b[1]));
}

__device__ __forceinline__ void cp16(uint32_t smem_addr, const void* gptr) {
    asm volatile("cp.async.cg.shared.global [%0], [%1], 16;\n"
                 :: "r"(smem_addr), "l"(gptr));
}

template <int SPLIT_HEADS>
__global__ __launch_bounds__(256) void gemm_tf32_kernel(
    const float* __restrict__ X, const float* __restrict__ W,
    float* __restrict__ Y)
{
    __shared__ float As[2][GBUF];
    __shared__ float Bs[2][GBUF];

    const int tid = threadIdx.x;
    const int bm = blockIdx.y * 128;
    const int bn = blockIdx.x * 128;
    const int lane = tid & 31;
    const int warp = tid >> 5;
    const int wm = (warp >> 2) * 64;   // warp M offset within block tile
    const int wn = (warp & 3) * 32;    // warp N offset
    const int gid = lane >> 2;         // 0..7
    const int tig = lane & 3;          // 0..3

    // cp.async chunk mapping: 512 16B-chunks per operand per tile; 2/thread
    const int r0c = (tid) >> 2, k0c = (tid & 3) * 4;
    const int r1c = (tid + 256) >> 2, k1c = ((tid + 256) & 3) * 4;

    uint32_t sA[2][2], sB[2][2];
    {
        uint32_t aBase0 = (uint32_t)__cvta_generic_to_shared(&As[0][0]);
        uint32_t aBase1 = (uint32_t)__cvta_generic_to_shared(&As[1][0]);
        uint32_t bBase0 = (uint32_t)__cvta_generic_to_shared(&Bs[0][0]);
        uint32_t bBase1 = (uint32_t)__cvta_generic_to_shared(&Bs[1][0]);
        sA[0][0] = aBase0 + (r0c * GSTRIDE + k0c) * 4;
        sA[0][1] = aBase0 + (r1c * GSTRIDE + k1c) * 4;
        sA[1][0] = aBase1 + (r0c * GSTRIDE + k0c) * 4;
        sA[1][1] = aBase1 + (r1c * GSTRIDE + k1c) * 4;
        sB[0][0] = bBase0 + (r0c * GSTRIDE + k0c) * 4;
        sB[0][1] = bBase0 + (r1c * GSTRIDE + k1c) * 4;
        sB[1][0] = bBase1 + (r0c * GSTRIDE + k0c) * 4;
        sB[1][1] = bBase1 + (r1c * GSTRIDE + k1c) * 4;
    }

    float acc[4][4][4];
#pragma unroll
    for (int mi = 0; mi < 4; mi++)
#pragma unroll
        for (int ni = 0; ni < 4; ni++)
#pragma unroll
            for (int r = 0; r < 4; r++) acc[mi][ni][r] = 0.f;

    // prologue: tile 0 -> buf 0
    {
        cp16(sA[0][0], X + (size_t)(bm + r0c) * DD + k0c);
        cp16(sA[0][1], X + (size_t)(bm + r1c) * DD + k1c);
        cp16(sB[0][0], W + (size_t)(bn + r0c) * DD + k0c);
        cp16(sB[0][1], W + (size_t)(bn + r1c) * DD + k1c);
        asm volatile("cp.async.commit_group;\n" ::: "memory");
    }

    const int NT = DD / GBK;  // 64
    for (int t = 0; t < NT; t++) {
        asm volatile("cp.async.wait_group 0;\n" ::: "memory");
        __syncthreads();

        if (t + 1 < NT) {
            const int kt = (t + 1) * GBK;
            const int nb = (t + 1) & 1;
            cp16(sA[nb][0], X + (size_t)(bm + r0c) * DD + kt + k0c);
            cp16(sA[nb][1], X + (size_t)(bm + r1c) * DD + kt + k1c);
            cp16(sB[nb][0], W + (size_t)(bn + r0c) * DD + kt + k0c);
            cp16(sB[nb][1], W + (size_t)(bn + r1c) * DD + kt + k1c);
            asm volatile("cp.async.commit_group;\n" ::: "memory");
        }

        const float* Ab = As[t & 1];
        const float* Bb = Bs[t & 1];
#pragma unroll
        for (int step = 0; step < 2; step++) {
            const int k0 = step * 8 + tig;
            uint32_t a[4][4], b[4][2];
#pragma unroll
            for (int mi = 0; mi < 4; mi++) {
                const float* pa = Ab + (wm + mi * 16 + gid) * GSTRIDE + k0;
                a[mi][0] = f2tf32(pa[0]);
                a[mi][1] = f2tf32(pa[8 * GSTRIDE]);
                a[mi][2] = f2tf32(pa[4]);
                a[mi][3] = f2tf32(pa[8 * GSTRIDE + 4]);
            }
#pragma unroll
            for (int ni = 0; ni < 4; ni++) {
                const float* pb = Bb + (wn + ni * 8 + gid) * GSTRIDE + k0;
                b[ni][0] = f2tf32(pb[0]);
                b[ni][1] = f2tf32(pb[4]);
            }
#pragma unroll
            for (int mi = 0; mi < 4; mi++)
#pragma unroll
                for (int ni = 0; ni < 4; ni++)
                    mma_tf32(acc[mi][ni], a[mi], b[ni]);
        }
        __syncthreads();
    }

    // epilogue
#pragma unroll
    for (int mi = 0; mi < 4; mi++) {
#pragma unroll
        for (int ni = 0; ni < 4; ni++) {
            int r0 = bm + wm + mi * 16 + gid;
            int c0 = bn + wn + ni * 8 + tig * 2;
            float2 lo = make_float2(acc[mi][ni][0], acc[mi][ni][1]);
            float2 hi = make_float2(acc[mi][ni][2], acc[mi][ni][3]);
            if (SPLIT_HEADS) {
                int b = r0 >> 11, l = r0 & 2047;
                int h = c0 >> 6, hd = c0 & 63;
                float* d0 = g_Qh; // placeholder, overwritten below via Y
                (void)d0;
                float* dst0 = Y + (((size_t)(b * HH + h) * LL + l) * HD + hd);
                float* dst1 = Y + (((size_t)(b * HH + h) * LL + (l))) * 0; // unused
                (void)dst1;
                *(float2*)dst0 = lo;
                int r1 = r0 + 8;
                int b1 = r1 >> 11, l1 = r1 & 2047;
                float* dsth = Y + (((size_t)(b1 * HH + h) * LL + l1) * HD + hd);
                *(float2*)dsth = hi;
            } else {
                *(float2*)(Y + (size_t)r0 * DD + c0) = lo;
                *(float2*)(Y + (size_t)(r0 + 8) * DD + c0) = hi;
            }
        }
    }
}

// ---------------------------------------------------------------------------
// Flash attention (causal). 1 thread = 1 query row. BM=128 queries/block,
// key tiles of 64. Online softmax in 8-key chunks. (unchanged from R1)
// ---------------------------------------------------------------------------
__global__ __launch_bounds__(128) void flash_attn_kernel(
    const float* __restrict__ Qh, const float* __restrict__ Kh,
    const float* __restrict__ Vh, float* __restrict__ AO)
{
    __shared__ float Ks[64][HD + 4];
    __shared__ float Vs[64][HD + 4];

    const int bh = blockIdx.y;          // b*H + h
    const int b = bh >> 4;
    const int h = bh & 15;
    const int l = blockIdx.x * 128 + threadIdx.x;

    const float* Qb = Qh + (size_t)bh * (LL * HD);
    const float* Kb = Kh + (size_t)bh * (SS * HD);
    const float* Vb = Vh + (size_t)bh * (SS * HD);

    float q[64], o[64];
#pragma unroll
    for (int i = 0; i < 16; i++) {
        float4 t = *(const float4*)(Qb + (size_t)l * HD + i * 4);
        q[4 * i + 0] = t.x; q[4 * i + 1] = t.y;
        q[4 * i + 2] = t.z; q[4 * i + 3] = t.w;
    }
#pragma unroll
    for (int d = 0; d < 64; d++) o[d] = 0.f;

    float mx = -1e30f, lsum = 0.f;
    const int ntiles = blockIdx.x * 2 + 2;

    for (int jt = 0; jt < ntiles; jt++) {
        const int s0 = jt * 64;
        __syncthreads();
#pragma unroll
        for (int i = 0; i < 8; i++) {
            int t = threadIdx.x + i * 128;
            int r = t >> 4;
            int c = (t & 15) * 4;
            *(float4*)(&Ks[r][c]) = *(const float4*)(Kb + (size_t)(s0 + r) * HD + c);
            *(float4*)(&Vs[r][c]) = *(const float4*)(Vb + (size_t)(s0 + r) * HD + c);
        }
        __syncthreads();

#pragma unroll 1
        for (int c0 = 0; c0 < 64; c0 += 8) {
            float sc[8];
            float cm = -1e30f;
#pragma unroll
            for (int s = 0; s < 8; s++) {
                float a0 = 0.f, a1 = 0.f, a2 = 0.f, a3 = 0.f;
#pragma unroll
                for (int d4 = 0; d4 < 16; d4++) {
                    float4 kk = *(const float4*)(&Ks[c0 + s][d4 * 4]);
                    a0 += q[d4 * 4 + 0] * kk.x;
                    a1 += q[d4 * 4 + 1] * kk.y;
                    a2 += q[d4 * 4 + 2] * kk.z;
                    a3 += q[d4 * 4 + 3] * kk.w;
                }
                float v = ((a0 + a1) + (a2 + a3)) * 0.125f;
                if (s0 + c0 + s > l) v = -1e30f;
                sc[s] = v;
                cm = fmaxf(cm, v);
            }
            float mnew = fmaxf(mx, cm);
            if (mnew != mx) {
                float corr = __expf(mx - mnew);
                lsum *= corr;
#pragma unroll
                for (int d = 0; d < 64; d++) o[d] *= corr;
                mx = mnew;
            }
#pragma unroll
            for (int s = 0; s < 8; s++) {
                float p = __expf(sc[s] - mx);
                lsum += p;
#pragma unroll
                for (int d4 = 0; d4 < 16; d4++) {
                    float4 vv = *(const float4*)(&Vs[c0 + s][d4 * 4]);
                    o[d4 * 4 + 0] += p * vv.x;
                    o[d4 * 4 + 1] += p * vv.y;
                    o[d4 * 4 + 2] += p * vv.z;
                    o[d4 * 4 + 3] += p * vv.w;
                }
            }
        }
    }

    const float inv = 1.f / lsum;
    float* dst = AO + ((size_t)(b * LL) + l) * DD + h * HD;
#pragma unroll
    for (int i = 0; i < 16; i++) {
        float4 t = make_float4(o[4 * i + 0] * inv, o[4 * i + 1] * inv,
                               o[4 * i + 2] * inv, o[4 * i + 3] * inv);
        *(float4*)(dst + 4 * i) = t;
    }
}

// ---------------------------------------------------------------------------
// Launch
// ---------------------------------------------------------------------------
extern "C" void kernel_launch(void* const* d_in, const int* in_sizes, int n_in,
                              void* d_out, int out_size)
{
    const float* q  = (const float*)d_in[0];
    const float* k  = (const float*)d_in[1];
    const float* v  = (const float*)d_in[2];
    // d_in[3] = mask (causal, known analytically — unused)
    const float* Wq = (const float*)d_in[4];
    const float* Wk = (const float*)d_in[5];
    const float* Wv = (const float*)d_in[6];
    const float* Wo = (const float*)d_in[7];
    float* out = (float*)d_out;

    float *Qh, *Kh, *Vh, *AO;
    cudaGetSymbolAddress((void**)&Qh, g_Qh);
    cudaGetSymbolAddress((void**)&Kh, g_Kh);
    cudaGetSymbolAddress((void**)&Vh, g_Vh);
    cudaGetSymbolAddress((void**)&AO, g_AO);

    dim3 ggrid(DD / 128, MM / 128);   // (8, 64)
    dim3 gblk(256);

    // Projections with fused head-split transpose (TF32 tensor cores)
    gemm_tf32_kernel<1><<<ggrid, gblk>>>(q, Wq, Qh);
    gemm_tf32_kernel<1><<<ggrid, gblk>>>(k, Wk, Kh);
    gemm_tf32_kernel<1><<<ggrid, gblk>>>(v, Wv, Vh);

    // Causal flash attention -> AO [B,L,D]
    dim3 fgrid(LL / 128, BB * HH);    // (16, 64)
    flash_attn_kernel<<<fgrid, 128>>>(Qh, Kh, Vh, AO);

    // Output projection -> d_out (TF32 tensor cores)
    gemm_tf32_kernel<0><<<ggrid, gblk>>>(AO, Wo, out);
}